// round 6
// baseline (speedup 1.0000x reference)
#include <cuda_runtime.h>
#include <cstdint>

// ---------------------------------------------------------------------------
// NeuralSplineFourierFilter: tiny MLP on scalar 'a' -> 16 knots + 18 control
// points -> degree-3 B-spline evaluated on a 256^3 grid.
//
//   setup_kernel  : MLP + softmax/cumsum knots + symbolic de Boor to build
//                   per-segment cubic polynomials in LOCAL coords (u = x - k[s])
//   lut_kernel    : 4096-bin segment lookup table over [0,1)
//   eval_kernel   : hot loop, float4 vectorized, LUT + Horner, memory-bound
// ---------------------------------------------------------------------------

#define NSEG   15          // active segments (s = 0..14)
#define NLUT   4096

// 16-byte alignment is load-bearing: these are read via float4/uint4.
__device__ __align__(16) float        g_segPoly[NSEG * 4]; // p0,p1,p2,p3 per segment
__device__ __align__(16) float        g_segLo[NSEG + 1];   // k[s] (local origin)
__device__ __align__(16) float        g_segHi[NSEG + 1];   // k[s+1] (refine bound)
__device__ __align__(16) float        g_knots[16];         // k[0..15]
__device__ __align__(16) unsigned char g_lut[NLUT];

// ---------------------------------------------------------------------------
// Kernel 1: everything scalar-sized. 1 block, 32 threads.
// ---------------------------------------------------------------------------
__global__ void setup_kernel(const float* __restrict__ a_in,
                             const float* __restrict__ W1, const float* __restrict__ b1,
                             const float* __restrict__ W2, const float* __restrict__ b2,
                             const float* __restrict__ Ww, const float* __restrict__ bw,
                             const float* __restrict__ Wk, const float* __restrict__ bk)
{
    __shared__ float s_net[32], s_net2[32], s_w[17], s_klog[15];
    __shared__ float s_k[16], s_c[18];
    const int t = threadIdx.x;

    const float a = a_in[0];
    s_net[t] = sinf(fmaf(a, W1[t], b1[t]));
    __syncthreads();

    {
        float acc = b2[t];
        #pragma unroll
        for (int j = 0; j < 32; ++j) acc = fmaf(s_net[j], W2[j * 32 + t], acc);
        s_net2[t] = sinf(acc);
    }
    __syncthreads();

    if (t < 17) {
        float w = bw[t];
        #pragma unroll
        for (int j = 0; j < 32; ++j) w = fmaf(s_net2[j], Ww[j * 17 + t], w);
        s_w[t] = w;
    }
    if (t < 15) {
        float kk = bk[t];
        #pragma unroll
        for (int j = 0; j < 32; ++j) kk = fmaf(s_net2[j], Wk[j * 15 + t], kk);
        s_klog[t] = kk;
    }
    __syncthreads();

    if (t == 0) {
        // softmax + cumsum -> monotone knots in (0,1], prepend 0
        float m = s_klog[0];
        for (int i = 1; i < 15; ++i) m = fmaxf(m, s_klog[i]);
        float e[15], sum = 0.f;
        for (int i = 0; i < 15; ++i) { e[i] = expf(s_klog[i] - m); sum += e[i]; }
        const float inv = 1.0f / sum;
        float cs = 0.f;
        s_k[0] = 0.f;
        for (int i = 0; i < 15; ++i) { cs += e[i] * inv; s_k[i + 1] = cs; }
        s_c[0] = 0.f;
        for (int i = 0; i < 17; ++i) s_c[i + 1] = s_w[i];
    }
    __syncthreads();

    if (t < 16) g_knots[t] = s_k[t];

    // Symbolic de Boor per segment: polynomial in u = x - k[s], double precision.
    if (t < NSEG) {
        double T[22];
        for (int i = 0; i < 3; ++i)  T[i] = 0.0;
        for (int i = 0; i < 16; ++i) T[3 + i] = (double)s_k[i];
        for (int i = 19; i < 22; ++i) T[i] = 1.0;

        const int s = t;                 // kidx = s + 3
        const double x0 = T[s + 3];      // = k[s]

        double D[4][4];
        for (int j = 0; j < 4; ++j) {
            D[j][0] = (double)s_c[s + j];
            D[j][1] = D[j][2] = D[j][3] = 0.0;
        }
        for (int r = 1; r <= 3; ++r) {
            for (int j = 3; j >= r; --j) {
                const double tlo = T[j + s];
                const double thi = T[j + 1 + s + 3 - r];
                const double A = 1.0 / (thi - tlo);
                const double B = A * (x0 - tlo);      // alpha(u) = A*u + B
                double nf[4];
                for (int m2 = 0; m2 < 4; ++m2) {
                    const double dm  = D[j][m2] - D[j - 1][m2];
                    const double dm1 = (m2 > 0) ? (D[j][m2 - 1] - D[j - 1][m2 - 1]) : 0.0;
                    nf[m2] = D[j - 1][m2] + B * dm + A * dm1;
                }
                for (int m2 = 0; m2 < 4; ++m2) D[j][m2] = nf[m2];
            }
        }
        g_segPoly[4 * s + 0] = (float)D[3][0];
        g_segPoly[4 * s + 1] = (float)D[3][1];
        g_segPoly[4 * s + 2] = (float)D[3][2];
        g_segPoly[4 * s + 3] = (float)D[3][3];
        g_segLo[s] = (float)x0;
        g_segHi[s] = s_k[s + 1];
    }
}

// ---------------------------------------------------------------------------
// Kernel 2: segment LUT.  lut[b] = #{ i in 1..15 : k[i] <= b/NLUT }, clamp 14.
// Conservative lower bound for any xc in the bin; eval refines forward.
// ---------------------------------------------------------------------------
__global__ void lut_kernel()
{
    const int b = blockIdx.x * blockDim.x + threadIdx.x;
    if (b >= NLUT) return;
    const float xb = (float)b * (1.0f / (float)NLUT);
    int s = 0;
    #pragma unroll
    for (int i = 1; i < 16; ++i) s += (g_knots[i] <= xb) ? 1 : 0;
    if (s > NSEG - 1) s = NSEG - 1;
    g_lut[b] = (unsigned char)s;
}

// ---------------------------------------------------------------------------
// Kernel 3: hot loop.
// ---------------------------------------------------------------------------
__device__ __forceinline__ float eval_one(float xi,
                                          const float4* __restrict__ sPoly,
                                          const float* __restrict__ sLo,
                                          const float* __restrict__ sHi,
                                          const unsigned char* __restrict__ sLut)
{
    const float INV_SQRT3 = 0.5773502691896258f;
    float xc = fminf(fmaxf(xi * INV_SQRT3, 0.0f), 0.99990000f);
    int b = (int)(xc * (float)NLUT);
    int s = sLut[b];
    #pragma unroll 1
    while (s < NSEG - 1 && xc >= sHi[s]) ++s;   // rare: bin contains a knot
    const float4 p = sPoly[s];
    const float u = xc - sLo[s];
    return fmaf(fmaf(fmaf(p.w, u, p.z), u, p.y), u, p.x);
}

// Shared tables loader. sLutVec is uint4-typed so its 16-byte alignment is
// structural (the R3/R4 trap was an STS.128 into a char[] at a non-16B-aligned
// shared offset).
struct __align__(16) SharedTables {
    float4 poly[NSEG + 1];
    uint4  lutVec[NLUT / 16];
    float  lo[NSEG + 1];
    float  hi[NSEG + 1];
};

__device__ __forceinline__ void load_tables(SharedTables& st, int tid, int nthreads)
{
    if (tid < NSEG) {
        st.poly[tid] = reinterpret_cast<const float4*>(g_segPoly)[tid];
        st.lo[tid]   = g_segLo[tid];
        st.hi[tid]   = g_segHi[tid];
    }
    for (int i = tid; i < NLUT / 16; i += nthreads)
        st.lutVec[i] = reinterpret_cast<const uint4*>(g_lut)[i];
    __syncthreads();
}

__global__ void __launch_bounds__(256)
eval_kernel(const float4* __restrict__ x4, float4* __restrict__ o4, int n4)
{
    __shared__ SharedTables st;
    const int tid = threadIdx.x;
    load_tables(st, tid, 256);
    const unsigned char* sLut = reinterpret_cast<const unsigned char*>(st.lutVec);

    const int stride = gridDim.x * blockDim.x;
    for (int i = blockIdx.x * blockDim.x + tid; i < n4; i += stride) {
        const float4 xv = x4[i];
        float4 r;
        r.x = eval_one(xv.x, st.poly, st.lo, st.hi, sLut);
        r.y = eval_one(xv.y, st.poly, st.lo, st.hi, sLut);
        r.z = eval_one(xv.z, st.poly, st.lo, st.hi, sLut);
        r.w = eval_one(xv.w, st.poly, st.lo, st.hi, sLut);
        o4[i] = r;
    }
}

// Scalar-I/O variants (tail elements, and full fallback if harness pointers
// are ever not 16-byte aligned).
__global__ void __launch_bounds__(256)
eval_kernel_scalar(const float* __restrict__ x, float* __restrict__ out,
                   int start, int n)
{
    __shared__ SharedTables st;
    const int tid = threadIdx.x;
    load_tables(st, tid, 256);
    const unsigned char* sLut = reinterpret_cast<const unsigned char*>(st.lutVec);

    const int stride = gridDim.x * blockDim.x;
    for (int j = start + blockIdx.x * blockDim.x + tid; j < n; j += stride)
        out[j] = eval_one(x[j], st.poly, st.lo, st.hi, sLut);
}

// ---------------------------------------------------------------------------
extern "C" void kernel_launch(void* const* d_in, const int* in_sizes, int n_in,
                              void* d_out, int out_size)
{
    const float* x  = (const float*)d_in[0];
    const float* a  = (const float*)d_in[1];
    const float* W1 = (const float*)d_in[2];
    const float* b1 = (const float*)d_in[3];
    const float* W2 = (const float*)d_in[4];
    const float* b2 = (const float*)d_in[5];
    const float* Ww = (const float*)d_in[6];
    const float* bw = (const float*)d_in[7];
    const float* Wk = (const float*)d_in[8];
    const float* bk = (const float*)d_in[9];
    float* out = (float*)d_out;
    const int n = in_sizes[0];

    setup_kernel<<<1, 32>>>(a, W1, b1, W2, b2, Ww, bw, Wk, bk);
    lut_kernel<<<NLUT / 256, 256>>>();

    const bool aligned16 =
        ((((uintptr_t)x) | ((uintptr_t)out)) & 0xF) == 0;

    if (aligned16) {
        const int n4 = n >> 2;
        int blocks = (n4 + 255) / 256;
        if (blocks > 1536) blocks = 1536;
        if (blocks < 1) blocks = 1;
        if (n4 > 0)
            eval_kernel<<<blocks, 256>>>(reinterpret_cast<const float4*>(x),
                                         reinterpret_cast<float4*>(out), n4);
        if ((n4 << 2) < n)   // tail (none for 256^3)
            eval_kernel_scalar<<<1, 256>>>(x, out, n4 << 2, n);
    } else {
        int blocks = (n + 255) / 256;
        if (blocks > 1536) blocks = 1536;
        eval_kernel_scalar<<<blocks, 256>>>(x, out, 0, n);
    }
}